// round 3
// baseline (speedup 1.0000x reference)
#include <cuda_runtime.h>
#include <cuda_bf16.h>
#include <cstdint>

#define DEV_INLINE __device__ __forceinline__

constexpr int N_PTS  = 131072;
constexpr int K_CL   = 256;
constexpr int D_DIM  = 32;

constexpr int TILE_M = 128;                 // points per CTA
constexpr int KTOT   = 608;                 // 528 pairs + 32 linear + 48 pad
constexpr int NCH    = KTOT / 32;           // 19 chunks of 32 k-columns
constexpr int U_CHUNK = K_CL * 64;          // 256 rows x 64B = 16384
constexpr int F_CHUNK = TILE_M * 64;        // 128 rows x 64B = 8192

// ---------------- device-global scratch ----------------
__device__ __align__(128) unsigned char U_g[NCH * U_CHUNK]; // pre-swizzled bf16 B operand
__device__ unsigned short tab_g[KTOT];   // low byte = d, high byte = e (index 32 => constant 1.0)
__device__ float g_g[K_CL];
__device__ float wsum_g;
__device__ float C_g;

// ---------------- helpers ----------------
DEV_INLINE uint32_t smem_u32(const void* p) {
    uint32_t a;
    asm("{ .reg .u64 t; cvta.to.shared.u64 t, %1; cvt.u32.u64 %0, t; }" : "=r"(a) : "l"(p));
    return a;
}
// row-dependent swizzle for 64B rows: rotate 16B chunks by (row>>1)&3
DEV_INLINE uint32_t swz(uint32_t c, uint32_t row) { return c ^ ((row & 6u) << 3); }

DEV_INLINE uint32_t lds_u32(uint32_t a) {
    uint32_t v; asm volatile("ld.shared.b32 %0, [%1];" : "=r"(v) : "r"(a)); return v;
}
DEV_INLINE void sts_u32(uint32_t a, uint32_t v) {
    asm volatile("st.shared.b32 [%0], %1;" :: "r"(a), "r"(v) : "memory");
}
DEV_INLINE void cp_async16(uint32_t dst, const void* src) {
    asm volatile("cp.async.cg.shared.global [%0], [%1], 16;"
                 :: "r"(dst), "l"(__cvta_generic_to_global(src)) : "memory");
}
#define CP_COMMIT() asm volatile("cp.async.commit_group;" ::: "memory")
#define CP_WAIT0()  asm volatile("cp.async.wait_group 0;" ::: "memory")

DEV_INLINE void mma16816(float* c, const uint32_t* a, uint32_t b0, uint32_t b1) {
    asm volatile(
        "mma.sync.aligned.m16n8k16.row.col.f32.bf16.bf16.f32 "
        "{%0,%1,%2,%3}, {%4,%5,%6,%7}, {%8,%9}, {%0,%1,%2,%3};"
        : "+f"(c[0]), "+f"(c[1]), "+f"(c[2]), "+f"(c[3])
        : "r"(a[0]), "r"(a[1]), "r"(a[2]), "r"(a[3]), "r"(b0), "r"(b1));
}

// ---------------- setup: wsum + pair table ----------------
__global__ void k_setup(const float* __restrict__ w) {
    __shared__ float sh[256];
    int t = threadIdx.x;
    sh[t] = fabsf(w[t]);
    __syncthreads();
    for (int s = 128; s > 0; s >>= 1) { if (t < s) sh[t] += sh[t + s]; __syncthreads(); }
    if (t == 0) wsum_g = sh[0] + 1e-30f;

    for (int p = t; p < KTOT; p += 256) {
        int d, e;
        if (p < 528) {
            // pairs (d,e) with d<=e, enumerated d-major
            int dd = 0, base = 0;
            while (dd < 31 && base + (32 - dd) <= p) { base += 32 - dd; dd++; }
            d = dd; e = dd + (p - base);
        } else if (p < 560) {
            d = p - 528; e = 32;          // linear term: x_d * 1
        } else {
            d = 32; e = 32;               // padding (U=0)
        }
        tab_g[p] = (unsigned short)(d | (e << 8));
    }
}

// ---------------- per-cluster prep: A, U (bf16 swizzled), Cholesky logdet, g_k ----------------
__global__ void k_prep(const float* __restrict__ centers,
                       const float* __restrict__ S,
                       const float* __restrict__ w) {
    __shared__ float Ssh[D_DIM * D_DIM];
    __shared__ float Ash[D_DIM * 33];
    __shared__ float csh[D_DIM];
    __shared__ float msh[D_DIM];
    int k = blockIdx.x, t = threadIdx.x;

    #pragma unroll
    for (int q = 0; q < 4; q++) Ssh[t + 256 * q] = S[k * 1024 + t + 256 * q];
    if (t < 32) csh[t] = centers[k * 32 + t];
    __syncthreads();

    #pragma unroll
    for (int q = 0; q < 4; q++) {
        int idx = t + 256 * q;
        int d = idx >> 5, f = idx & 31;
        float a = 0.f;
        #pragma unroll
        for (int e = 0; e < 32; e++) a += Ssh[d * 32 + e] * Ssh[f * 32 + e];
        Ash[d * 33 + f] = a;
    }
    __syncthreads();

    if (t < 32) {
        float m = 0.f;
        #pragma unroll
        for (int f = 0; f < 32; f++) m += Ash[t * 33 + f] * csh[f];
        msh[t] = m;
    }
    __syncthreads();

    // U entries, written into the swizzled SMEM-image layout
    for (int p = t; p < KTOT; p += 256) {
        unsigned short de = tab_g[p];
        int d = de & 255, e = de >> 8;
        float val;
        if (p < 528)      val = (d == e) ? -0.5f * Ash[d * 33 + e] : -Ash[d * 33 + e];
        else if (p < 560) val = msh[d];
        else              val = 0.f;
        uint32_t off = (uint32_t)(p >> 5) * U_CHUNK + (uint32_t)k * 64 + swz((uint32_t)(p & 31) * 2, (uint32_t)k);
        *reinterpret_cast<__nv_bfloat16*>(U_g + off) = __float2bfloat16(val);
    }
    __syncthreads();

    if (t < 32) {
        float cAc = msh[t] * csh[t];
        #pragma unroll
        for (int o = 16; o > 0; o >>= 1) cAc += __shfl_xor_sync(0xffffffff, cAc, o);
        // warp Cholesky (SPD), lane = row
        float halflogdet = 0.f;
        for (int j = 0; j < 32; j++) {
            float ljj = sqrtf(Ash[j * 33 + j]);
            halflogdet += logf(ljj);
            float lij = (t > j) ? Ash[t * 33 + j] / ljj : 0.f;
            if (t > j) Ash[t * 33 + j] = lij;
            __syncwarp();
            if (t > j) {
                for (int c2 = j + 1; c2 <= t; c2++)
                    Ash[t * 33 + c2] -= lij * Ash[c2 * 33 + j];
            }
            __syncwarp();
        }
        if (t == 0)
            g_g[k] = logf(fabsf(w[k]) / wsum_g) + halflogdet - 0.5f * cAc;
    }
}

__global__ void k_maxg() {
    __shared__ float sh[256];
    int t = threadIdx.x;
    sh[t] = g_g[t];
    __syncthreads();
    for (int s = 128; s > 0; s >>= 1) { if (t < s) sh[t] = fmaxf(sh[t], sh[t + s]); __syncthreads(); }
    if (t == 0) C_g = sh[0];
}

// ---------------- main fused GEMM + logsumexp ----------------
constexpr int SMEM_U   = 0;               // 2 x 16384
constexpr int SMEM_F   = 32768;           // 2 x 8192
constexpr int SMEM_X   = 49152;           // 128 x 33 f32 = 16896
constexpr int SMEM_G   = 66048;           // 256 f32
constexpr int SMEM_P   = 67072;           // 128 x 4 f32
constexpr int SMEM_TAB = 69120;           // 608 u16
constexpr int SMEM_DYN = 70336 + 1024;

__global__ __launch_bounds__(256, 1)
void k_main(const float* __restrict__ points,
            const float* __restrict__ thr_p,
            float* __restrict__ out) {
    extern __shared__ char smem_raw[];
    char* smem = (char*)(((uintptr_t)smem_raw + 1023) & ~(uintptr_t)1023);
    uint32_t sb = smem_u32(smem);
    int tid = threadIdx.x;
    int wid = tid >> 5, lane = tid & 31;
    int g = lane >> 2, t4 = lane & 3;
    int warp_r = wid >> 2, warp_c = wid & 3;   // rows 64*warp_r, cols 64*warp_c
    int i0 = blockIdx.x * TILE_M;

    float* Xs = (float*)(smem + SMEM_X);
    float* gs = (float*)(smem + SMEM_G);
    unsigned short* tab_s = (unsigned short*)(smem + SMEM_TAB);

    // loads: X tile (pad col 32 with 1.0), g, tab
    #pragma unroll
    for (int q = 0; q < 16; q++) {
        int lin = tid + 256 * q;               // 0..4095
        Xs[(lin >> 5) * 33 + (lin & 31)] = points[(size_t)i0 * 32 + lin];
    }
    if (tid < 128) Xs[tid * 33 + 32] = 1.0f;
    gs[tid] = g_g[tid];
    gs[tid + 128] = g_g[tid + 128]; // wait: 256 threads cover 256 directly
    for (int p = tid; p < KTOT; p += 256) tab_s[p] = tab_g[p];
    float Cv = C_g, thrv = thr_p[0];
    __syncthreads();

    // F generation lambda-equivalent: thread -> row r, half h
    int fr = tid >> 1, fh = tid & 1;
    const float* xr = Xs + fr * 33;

    auto gen_F = [&](int c, int stage) {
        uint32_t fb = sb + SMEM_F + (uint32_t)stage * F_CHUNK + (uint32_t)fr * 64;
        #pragma unroll
        for (int w = 0; w < 8; w++) {
            int q = c * 32 + fh * 16 + w * 2;
            unsigned short de0 = tab_s[q], de1 = tab_s[q + 1];
            float v0 = xr[de0 & 63] * xr[de0 >> 8];
            float v1 = xr[de1 & 63] * xr[de1 >> 8];
            __nv_bfloat162 p2 = __floats2bfloat162_rn(v0, v1);
            uint32_t cb = (uint32_t)(fh * 32 + w * 4);
            sts_u32(fb + swz(cb, (uint32_t)fr), *(uint32_t*)&p2);
        }
    };
    auto load_U = [&](int c, int stage) {
        const unsigned char* src = U_g + (size_t)c * U_CHUNK + (size_t)tid * 64;
        uint32_t dst = sb + SMEM_U + (uint32_t)stage * U_CHUNK + (uint32_t)tid * 64;
        cp_async16(dst, src);       cp_async16(dst + 16, src + 16);
        cp_async16(dst + 32, src + 32); cp_async16(dst + 48, src + 48);
        CP_COMMIT();
    };

    float acc[4][8][4];
    #pragma unroll
    for (int a = 0; a < 4; a++)
        #pragma unroll
        for (int b = 0; b < 8; b++)
            #pragma unroll
            for (int j = 0; j < 4; j++) acc[a][b][j] = 0.f;

    // prologue
    gen_F(0, 0);
    load_U(0, 0);

    for (int c = 0; c < NCH; c++) {
        int s = c & 1;
        CP_WAIT0();
        __syncthreads();
        if (c + 1 < NCH) { gen_F(c + 1, s ^ 1); load_U(c + 1, s ^ 1); }

        uint32_t fb = sb + SMEM_F + (uint32_t)s * F_CHUNK;
        uint32_t ub = sb + SMEM_U + (uint32_t)s * U_CHUNK;
        #pragma unroll
        for (int ks = 0; ks < 2; ks++) {
            uint32_t cbase = (uint32_t)(ks * 32 + t4 * 4);
            uint32_t a_frag[4][4];
            #pragma unroll
            for (int rt = 0; rt < 4; rt++) {
                uint32_t r0 = (uint32_t)(warp_r * 64 + rt * 16 + g);
                a_frag[rt][0] = lds_u32(fb + r0 * 64       + swz(cbase,      r0));
                a_frag[rt][1] = lds_u32(fb + (r0 + 8) * 64 + swz(cbase,      r0 + 8));
                a_frag[rt][2] = lds_u32(fb + r0 * 64       + swz(cbase + 16, r0));
                a_frag[rt][3] = lds_u32(fb + (r0 + 8) * 64 + swz(cbase + 16, r0 + 8));
            }
            #pragma unroll
            for (int ct = 0; ct < 8; ct++) {
                uint32_t n = (uint32_t)(warp_c * 64 + ct * 8 + g);
                uint32_t b0 = lds_u32(ub + n * 64 + swz(cbase,      n));
                uint32_t b1 = lds_u32(ub + n * 64 + swz(cbase + 16, n));
                #pragma unroll
                for (int rt = 0; rt < 4; rt++)
                    mma16816(acc[rt][ct], a_frag[rt], b0, b1);
            }
        }
    }

    // -------- epilogue: exp-sum, reduce, log --------
    float* part = (float*)(smem + SMEM_P);
    #pragma unroll
    for (int rt = 0; rt < 4; rt++) {
        float e_lo = 0.f, e_hi = 0.f;
        #pragma unroll
        for (int ct = 0; ct < 8; ct++) {
            int n0 = warp_c * 64 + ct * 8 + t4 * 2;
            float g0 = gs[n0] - Cv, g1 = gs[n0 + 1] - Cv;
            e_lo += __expf(acc[rt][ct][0] + g0) + __expf(acc[rt][ct][1] + g1);
            e_hi += __expf(acc[rt][ct][2] + g0) + __expf(acc[rt][ct][3] + g1);
        }
        e_lo += __shfl_xor_sync(0xffffffff, e_lo, 1);
        e_lo += __shfl_xor_sync(0xffffffff, e_lo, 2);
        e_hi += __shfl_xor_sync(0xffffffff, e_hi, 1);
        e_hi += __shfl_xor_sync(0xffffffff, e_hi, 2);
        if (t4 == 0) {
            int r = warp_r * 64 + rt * 16 + g;
            part[r * 4 + warp_c] = e_lo;
            part[(r + 8) * 4 + warp_c] = e_hi;
        }
    }
    __syncthreads();
    if (tid < 128) {
        float ssum = part[tid * 4] + part[tid * 4 + 1] + part[tid * 4 + 2] + part[tid * 4 + 3];
        out[i0 + tid] = logf(ssum) + Cv - thrv;
    }
}

// ---------------- launch ----------------
extern "C" void kernel_launch(void* const* d_in, const int* in_sizes, int n_in,
                              void* d_out, int out_size) {
    const float* points  = (const float*)d_in[0];
    const float* centers = (const float*)d_in[1];
    const float* covs    = (const float*)d_in[2];
    const float* weights = (const float*)d_in[3];
    const float* thresh  = (const float*)d_in[4];
    float* out = (float*)d_out;

    int n = in_sizes[0] / D_DIM;     // 131072
    int grid = n / TILE_M;           // 1024

    k_setup<<<1, 256>>>(weights);
    k_prep<<<K_CL, 256>>>(centers, covs, weights);
    k_maxg<<<1, 256>>>();

    cudaFuncSetAttribute(k_main, cudaFuncAttributeMaxDynamicSharedMemorySize, SMEM_DYN);
    k_main<<<grid, 256, SMEM_DYN>>>(points, thresh, out);
}

// round 4
// speedup vs baseline: 1.1352x; 1.1352x over previous
#include <cuda_runtime.h>
#include <cuda_bf16.h>
#include <cstdint>

#define DEV_INLINE __device__ __forceinline__

constexpr int N_PTS  = 131072;
constexpr int K_CL   = 256;
constexpr int D_DIM  = 32;

constexpr int TILE_M = 128;                 // points per CTA
constexpr int KTOT   = 608;                 // 528 pairs + 32 linear + 48 pad
constexpr int NCH    = KTOT / 32;           // 19 chunks of 32 k-columns
constexpr int U_CHUNK = K_CL * 64;          // 256 rows x 64B = 16384
constexpr int F_CHUNK = TILE_M * 64;        // 128 rows x 64B = 8192

// ---------------- device-global scratch ----------------
__device__ __align__(128) unsigned char U_g[NCH * U_CHUNK]; // pre-swizzled bf16 B operand
__device__ unsigned short tab_g[KTOT];   // low byte = d, high byte = e (index 32 => 1.0)
__device__ float g_g[K_CL];              // g'_k = log|w_k| + 0.5 logdet(A_k) - 0.5 c^T A c

// ---------------- helpers ----------------
DEV_INLINE uint32_t smem_u32(const void* p) {
    uint32_t a;
    asm("{ .reg .u64 t; cvta.to.shared.u64 t, %1; cvt.u32.u64 %0, t; }" : "=r"(a) : "l"(p));
    return a;
}
// row-dependent swizzle for 64B rows: rotate 16B chunks by (row>>1)&3
DEV_INLINE uint32_t swz(uint32_t c, uint32_t row) { return c ^ ((row & 6u) << 3); }

DEV_INLINE void sts_v4(uint32_t a, uint32_t v0, uint32_t v1, uint32_t v2, uint32_t v3) {
    asm volatile("st.shared.v4.b32 [%0], {%1,%2,%3,%4};"
                 :: "r"(a), "r"(v0), "r"(v1), "r"(v2), "r"(v3) : "memory");
}
DEV_INLINE void cp_async16(uint32_t dst, const void* src) {
    asm volatile("cp.async.cg.shared.global [%0], [%1], 16;"
                 :: "r"(dst), "l"(__cvta_generic_to_global(src)) : "memory");
}
#define CP_COMMIT() asm volatile("cp.async.commit_group;" ::: "memory")
#define CP_WAIT0()  asm volatile("cp.async.wait_group 0;" ::: "memory")

DEV_INLINE void ldsm4(uint32_t* r, uint32_t addr) {
    asm volatile("ldmatrix.sync.aligned.m8n8.x4.shared.b16 {%0,%1,%2,%3}, [%4];"
                 : "=r"(r[0]), "=r"(r[1]), "=r"(r[2]), "=r"(r[3]) : "r"(addr));
}

DEV_INLINE void mma16816(float* c, const uint32_t* a, uint32_t b0, uint32_t b1) {
    asm volatile(
        "mma.sync.aligned.m16n8k16.row.col.f32.bf16.bf16.f32 "
        "{%0,%1,%2,%3}, {%4,%5,%6,%7}, {%8,%9}, {%0,%1,%2,%3};"
        : "+f"(c[0]), "+f"(c[1]), "+f"(c[2]), "+f"(c[3])
        : "r"(a[0]), "r"(a[1]), "r"(a[2]), "r"(a[3]), "r"(b0), "r"(b1));
}

DEV_INLINE void pair_from_p(int p, int& d, int& e) {
    if (p < 528) {
        int dd = 0, base = 0;
        while (dd < 31 && base + (32 - dd) <= p) { base += 32 - dd; dd++; }
        d = dd; e = dd + (p - base);
    } else if (p < 560) { d = p - 528; e = 32; }
    else                { d = 32;      e = 32; }
}

// ---------------- per-cluster prep ----------------
__global__ void k_prep(const float* __restrict__ centers,
                       const float* __restrict__ S,
                       const float* __restrict__ w) {
    __shared__ float Ssh[D_DIM * D_DIM];
    __shared__ float Ash[D_DIM * 33];
    __shared__ float csh[D_DIM];
    __shared__ float msh[D_DIM];
    int k = blockIdx.x, t = threadIdx.x;

    #pragma unroll
    for (int q = 0; q < 4; q++) Ssh[t + 256 * q] = S[k * 1024 + t + 256 * q];
    if (t < 32) csh[t] = centers[k * 32 + t];
    __syncthreads();

    #pragma unroll
    for (int q = 0; q < 4; q++) {
        int idx = t + 256 * q;
        int d = idx >> 5, f = idx & 31;
        float a = 0.f;
        #pragma unroll
        for (int e = 0; e < 32; e++) a += Ssh[d * 32 + e] * Ssh[f * 32 + e];
        Ash[d * 33 + f] = a;
    }
    __syncthreads();

    if (t < 32) {
        float m = 0.f;
        #pragma unroll
        for (int f = 0; f < 32; f++) m += Ash[t * 33 + f] * csh[f];
        msh[t] = m;
    }
    __syncthreads();

    // U entries (bf16, swizzled SMEM image); block 0 also publishes tab_g
    for (int p = t; p < KTOT; p += 256) {
        int d, e; pair_from_p(p, d, e);
        float val;
        if (p < 528)      val = (d == e) ? -0.5f * Ash[d * 33 + e] : -Ash[d * 33 + e];
        else if (p < 560) val = msh[d];
        else              val = 0.f;
        uint32_t off = (uint32_t)(p >> 5) * U_CHUNK + (uint32_t)k * 64 + swz((uint32_t)(p & 31) * 2, (uint32_t)k);
        *reinterpret_cast<__nv_bfloat16*>(U_g + off) = __float2bfloat16(val);
        if (k == 0) tab_g[p] = (unsigned short)(d | (e << 8));
    }
    __syncthreads();

    if (t < 32) {
        float cAc = msh[t] * csh[t];
        #pragma unroll
        for (int o = 16; o > 0; o >>= 1) cAc += __shfl_xor_sync(0xffffffff, cAc, o);
        // warp Cholesky (SPD), lane = row
        float halflogdet = 0.f;
        for (int j = 0; j < 32; j++) {
            float ljj = sqrtf(Ash[j * 33 + j]);
            halflogdet += logf(ljj);
            float lij = (t > j) ? Ash[t * 33 + j] / ljj : 0.f;
            if (t > j) Ash[t * 33 + j] = lij;
            __syncwarp();
            if (t > j) {
                for (int c2 = j + 1; c2 <= t; c2++)
                    Ash[t * 33 + c2] -= lij * Ash[c2 * 33 + j];
            }
            __syncwarp();
        }
        if (t == 0)
            g_g[k] = logf(fabsf(w[k]) + 1e-37f) + halflogdet - 0.5f * cAc;
    }
}

// ---------------- main fused GEMM + logsumexp ----------------
constexpr int SMEM_U   = 0;               // 2 x 16384
constexpr int SMEM_F   = 32768;           // 2 x 8192
constexpr int SMEM_X   = 49152;           // 128 x 33 f32 = 16896
constexpr int SMEM_G   = 66048;           // 256 f32
constexpr int SMEM_P   = 67072;           // 128 x 4 f32
constexpr int SMEM_TAB = 69120;           // 608 u16 = 1216
constexpr int SMEM_RED = 70336;           // 8 max + 8 sum floats
constexpr int SMEM_DYN = 70400 + 1024;

DEV_INLINE uint32_t pack2(const float* xr, uint32_t t) {
    float v0 = xr[t & 255u]         * xr[(t >> 8)  & 255u];
    float v1 = xr[(t >> 16) & 255u] * xr[(t >> 24) & 255u];
    __nv_bfloat162 p2 = __floats2bfloat162_rn(v0, v1);
    return *(uint32_t*)&p2;
}

__global__ __launch_bounds__(256, 1)
void k_main(const float* __restrict__ points,
            const float* __restrict__ wts,
            const float* __restrict__ thr_p,
            float* __restrict__ out) {
    extern __shared__ char smem_raw[];
    char* smem = (char*)(((uintptr_t)smem_raw + 1023) & ~(uintptr_t)1023);
    uint32_t sb = smem_u32(smem);
    int tid = threadIdx.x;
    int wid = tid >> 5, lane = tid & 31;
    int g = lane >> 2, t4 = lane & 3;
    int warp_r = wid >> 2, warp_c = wid & 3;   // rows 64*warp_r, cols 64*warp_c
    int i0 = blockIdx.x * TILE_M;

    float* Xs = (float*)(smem + SMEM_X);
    float* gs = (float*)(smem + SMEM_G);
    float* redm = (float*)(smem + SMEM_RED);
    float* reds = (float*)(smem + SMEM_RED + 32);
    unsigned short* tab_s = (unsigned short*)(smem + SMEM_TAB);

    // loads: X tile (col 32 = 1.0), g', weights, tab
    #pragma unroll
    for (int q = 0; q < 16; q++) {
        int lin = tid + 256 * q;               // 0..4095
        Xs[(lin >> 5) * 33 + (lin & 31)] = points[(size_t)i0 * 32 + lin];
    }
    if (tid < 128) Xs[tid * 33 + 32] = 1.0f;
    {
        float gv = g_g[tid];
        gs[tid] = gv;
        float wv = fabsf(wts[tid]);
        #pragma unroll
        for (int o = 16; o > 0; o >>= 1) {
            gv = fmaxf(gv, __shfl_xor_sync(0xffffffff, gv, o));
            wv += __shfl_xor_sync(0xffffffff, wv, o);
        }
        if (lane == 0) { redm[wid] = gv; reds[wid] = wv; }
    }
    for (int p = tid; p < KTOT; p += 256) tab_s[p] = tab_g[p];
    float thrv = thr_p[0];
    __syncthreads();

    // F generation: thread -> row fr, half fh (16 cols)
    int fr = tid >> 1, fh = tid & 1;
    const float* xr = Xs + fr * 33;
    uint32_t frmask = ((uint32_t)fr & 6u) << 3;
    uint32_t gen_base0 = (uint32_t)fr * 64 + (((uint32_t)fh * 32) ^ frmask);

    // ldmatrix address precompute
    uint32_t offA[2][4], offB[2][4];
    {
        uint32_t lane15 = (uint32_t)(lane & 15);
        uint32_t colA = (uint32_t)(lane & 16);
        #pragma unroll
        for (int rt = 0; rt < 4; rt++) {
            uint32_t row = (uint32_t)(warp_r * 64 + rt * 16) + lane15;
            uint32_t m = (row & 6u) << 3;
            #pragma unroll
            for (int ks = 0; ks < 2; ks++)
                offA[ks][rt] = row * 64 + (((uint32_t)ks * 32 + colA) ^ m);
        }
        uint32_t colB = ((uint32_t)(lane & 8)) << 1;
        #pragma unroll
        for (int pr = 0; pr < 4; pr++) {
            uint32_t n = (uint32_t)(warp_c * 64 + pr * 16) + (((uint32_t)lane >> 1) & 8u) + (uint32_t)(lane & 7);
            uint32_t m = (n & 6u) << 3;
            #pragma unroll
            for (int ks = 0; ks < 2; ks++)
                offB[ks][pr] = n * 64 + (((uint32_t)ks * 32 + colB) ^ m);
        }
    }

    auto gen_F = [&](int c, int stage) {
        uint32_t base = sb + SMEM_F + (uint32_t)stage * F_CHUNK + gen_base0;
        const uint4* tq = (const uint4*)(tab_s + c * 32 + fh * 16);
        #pragma unroll
        for (int seg = 0; seg < 2; seg++) {
            uint4 q = tq[seg];
            uint32_t o0 = pack2(xr, q.x);
            uint32_t o1 = pack2(xr, q.y);
            uint32_t o2 = pack2(xr, q.z);
            uint32_t o3 = pack2(xr, q.w);
            sts_v4(base ^ ((uint32_t)seg << 4), o0, o1, o2, o3);
        }
    };
    auto load_U = [&](int c, int stage) {
        const unsigned char* src = U_g + (size_t)c * U_CHUNK + (size_t)tid * 64;
        uint32_t dst = sb + SMEM_U + (uint32_t)stage * U_CHUNK + (uint32_t)tid * 64;
        cp_async16(dst, src);           cp_async16(dst + 16, src + 16);
        cp_async16(dst + 32, src + 32); cp_async16(dst + 48, src + 48);
        CP_COMMIT();
    };

    float acc[4][8][4];
    #pragma unroll
    for (int a = 0; a < 4; a++)
        #pragma unroll
        for (int b = 0; b < 8; b++)
            #pragma unroll
            for (int j = 0; j < 4; j++) acc[a][b][j] = 0.f;

    // prologue
    gen_F(0, 0);
    load_U(0, 0);

    for (int c = 0; c < NCH; c++) {
        int s = c & 1;
        CP_WAIT0();
        __syncthreads();

        uint32_t fb = sb + SMEM_F + (uint32_t)s * F_CHUNK;
        uint32_t ub = sb + SMEM_U + (uint32_t)s * U_CHUNK;

        // A fragments for both k-steps (latency hides under gen)
        uint32_t fA[2][4][4];
        #pragma unroll
        for (int ks = 0; ks < 2; ks++)
            #pragma unroll
            for (int rt = 0; rt < 4; rt++)
                ldsm4(fA[ks][rt], fb + offA[ks][rt]);

        // first B fragment
        uint32_t fBc[4], fBn[4];
        ldsm4(fBc, ub + offB[0][0]);

        if (c + 1 < NCH) { gen_F(c + 1, s ^ 1); load_U(c + 1, s ^ 1); }

        #pragma unroll
        for (int step = 0; step < 8; step++) {
            int ks = step >> 2, pr = step & 3;
            if (step < 7) {
                int ns = step + 1;
                ldsm4(fBn, ub + offB[ns >> 2][ns & 3]);
            }
            #pragma unroll
            for (int rt = 0; rt < 4; rt++) {
                mma16816(acc[rt][2 * pr],     fA[ks][rt], fBc[0], fBc[1]);
                mma16816(acc[rt][2 * pr + 1], fA[ks][rt], fBc[2], fBc[3]);
            }
            #pragma unroll
            for (int j = 0; j < 4; j++) fBc[j] = fBn[j];
        }
    }

    // -------- epilogue: exp-sum, reduce, log --------
    float Cv = fmaxf(fmaxf(fmaxf(redm[0], redm[1]), fmaxf(redm[2], redm[3])),
                     fmaxf(fmaxf(redm[4], redm[5]), fmaxf(redm[6], redm[7])));
    float LW = logf(reds[0] + reds[1] + reds[2] + reds[3] +
                    reds[4] + reds[5] + reds[6] + reds[7] + 1e-30f);

    float* part = (float*)(smem + SMEM_P);
    #pragma unroll
    for (int rt = 0; rt < 4; rt++) {
        float e_lo = 0.f, e_hi = 0.f;
        #pragma unroll
        for (int ct = 0; ct < 8; ct++) {
            int n0 = warp_c * 64 + ct * 8 + t4 * 2;
            float g0 = gs[n0] - Cv, g1 = gs[n0 + 1] - Cv;
            e_lo += __expf(acc[rt][ct][0] + g0) + __expf(acc[rt][ct][1] + g1);
            e_hi += __expf(acc[rt][ct][2] + g0) + __expf(acc[rt][ct][3] + g1);
        }
        e_lo += __shfl_xor_sync(0xffffffff, e_lo, 1);
        e_lo += __shfl_xor_sync(0xffffffff, e_lo, 2);
        e_hi += __shfl_xor_sync(0xffffffff, e_hi, 1);
        e_hi += __shfl_xor_sync(0xffffffff, e_hi, 2);
        if (t4 == 0) {
            int r = warp_r * 64 + rt * 16 + g;
            part[r * 4 + warp_c] = e_lo;
            part[(r + 8) * 4 + warp_c] = e_hi;
        }
    }
    __syncthreads();
    if (tid < 128) {
        float ssum = part[tid * 4] + part[tid * 4 + 1] + part[tid * 4 + 2] + part[tid * 4 + 3];
        out[i0 + tid] = logf(ssum) + Cv - LW - thrv;
    }
}

// ---------------- launch ----------------
extern "C" void kernel_launch(void* const* d_in, const int* in_sizes, int n_in,
                              void* d_out, int out_size) {
    const float* points  = (const float*)d_in[0];
    const float* centers = (const float*)d_in[1];
    const float* covs    = (const float*)d_in[2];
    const float* weights = (const float*)d_in[3];
    const float* thresh  = (const float*)d_in[4];
    float* out = (float*)d_out;

    int n = in_sizes[0] / D_DIM;     // 131072
    int grid = n / TILE_M;           // 1024

    k_prep<<<K_CL, 256>>>(centers, covs, weights);

    cudaFuncSetAttribute(k_main, cudaFuncAttributeMaxDynamicSharedMemorySize, SMEM_DYN);
    k_main<<<grid, 256, SMEM_DYN>>>(points, weights, thresh, out);
}

// round 5
// speedup vs baseline: 1.2290x; 1.0827x over previous
#include <cuda_runtime.h>
#include <cuda_bf16.h>
#include <cstdint>

#define DEV_INLINE __device__ __forceinline__

constexpr int N_PTS  = 131072;
constexpr int K_CL   = 256;
constexpr int D_DIM  = 32;

constexpr int TILE_M = 128;                 // points per CTA
constexpr int KTOT   = 608;                 // 528 pairs + 32 linear + 48 pad
constexpr int NCH    = KTOT / 32;           // 19 chunks of 32 k-columns
constexpr int U_CHUNK = K_CL * 64;          // 256 rows x 64B = 16384
constexpr int F_CHUNK = TILE_M * 64;        // 128 rows x 64B = 8192

// ---------------- device-global scratch ----------------
__device__ __align__(128) unsigned char U_g[NCH * U_CHUNK]; // pre-swizzled bf16 B operand
__device__ unsigned short tab_g[KTOT];   // low byte = d, high byte = e (index 32 => 1.0)
__device__ float g_g[K_CL];              // g'_k = log|w_k| + 0.5 logdet(A_k) - 0.5 c^T A c

// ---------------- helpers ----------------
DEV_INLINE uint32_t smem_u32(const void* p) {
    uint32_t a;
    asm("{ .reg .u64 t; cvta.to.shared.u64 t, %1; cvt.u32.u64 %0, t; }" : "=r"(a) : "l"(p));
    return a;
}
// row-dependent swizzle for 64B rows: rotate 16B chunks by (row>>1)&3
DEV_INLINE uint32_t swz(uint32_t c, uint32_t row) { return c ^ ((row & 6u) << 3); }

DEV_INLINE void sts_v4(uint32_t a, uint32_t v0, uint32_t v1, uint32_t v2, uint32_t v3) {
    asm volatile("st.shared.v4.b32 [%0], {%1,%2,%3,%4};"
                 :: "r"(a), "r"(v0), "r"(v1), "r"(v2), "r"(v3) : "memory");
}
DEV_INLINE void cp_async16(uint32_t dst, const void* src) {
    asm volatile("cp.async.cg.shared.global [%0], [%1], 16;"
                 :: "r"(dst), "l"(__cvta_generic_to_global(src)) : "memory");
}
#define CP_COMMIT() asm volatile("cp.async.commit_group;" ::: "memory")
#define CP_WAIT0()  asm volatile("cp.async.wait_group 0;" ::: "memory")

DEV_INLINE void ldsm4(uint32_t* r, uint32_t addr) {
    asm volatile("ldmatrix.sync.aligned.m8n8.x4.shared.b16 {%0,%1,%2,%3}, [%4];"
                 : "=r"(r[0]), "=r"(r[1]), "=r"(r[2]), "=r"(r[3]) : "r"(addr));
}

DEV_INLINE void mma16816(float* c, const uint32_t* a, uint32_t b0, uint32_t b1) {
    asm volatile(
        "mma.sync.aligned.m16n8k16.row.col.f32.bf16.bf16.f32 "
        "{%0,%1,%2,%3}, {%4,%5,%6,%7}, {%8,%9}, {%0,%1,%2,%3};"
        : "+f"(c[0]), "+f"(c[1]), "+f"(c[2]), "+f"(c[3])
        : "r"(a[0]), "r"(a[1]), "r"(a[2]), "r"(a[3]), "r"(b0), "r"(b1));
}

DEV_INLINE void pair_from_p(int p, int& d, int& e) {
    if (p < 528) {
        int dd = 0, base = 0;
        while (dd < 31 && base + (32 - dd) <= p) { base += 32 - dd; dd++; }
        d = dd; e = dd + (p - base);
    } else if (p < 560) { d = p - 528; e = 32; }
    else                { d = 32;      e = 32; }
}

// ---------------- per-cluster prep ----------------
__global__ void k_prep(const float* __restrict__ centers,
                       const float* __restrict__ S,
                       const float* __restrict__ w) {
    __shared__ float Ssh[D_DIM * D_DIM];
    __shared__ float Ash[D_DIM * 33];
    __shared__ float csh[D_DIM];
    __shared__ float msh[D_DIM];
    int k = blockIdx.x, t = threadIdx.x;

    #pragma unroll
    for (int q = 0; q < 4; q++) Ssh[t + 256 * q] = S[k * 1024 + t + 256 * q];
    if (t < 32) csh[t] = centers[k * 32 + t];
    __syncthreads();

    #pragma unroll
    for (int q = 0; q < 4; q++) {
        int idx = t + 256 * q;
        int d = idx >> 5, f = idx & 31;
        float a = 0.f;
        #pragma unroll
        for (int e = 0; e < 32; e++) a += Ssh[d * 32 + e] * Ssh[f * 32 + e];
        Ash[d * 33 + f] = a;
    }
    __syncthreads();

    if (t < 32) {
        float m = 0.f;
        #pragma unroll
        for (int f = 0; f < 32; f++) m += Ash[t * 33 + f] * csh[f];
        msh[t] = m;
    }
    __syncthreads();

    // U entries (bf16, swizzled SMEM image); block 0 also publishes tab_g
    for (int p = t; p < KTOT; p += 256) {
        int d, e; pair_from_p(p, d, e);
        float val;
        if (p < 528)      val = (d == e) ? -0.5f * Ash[d * 33 + e] : -Ash[d * 33 + e];
        else if (p < 560) val = msh[d];
        else              val = 0.f;
        uint32_t off = (uint32_t)(p >> 5) * U_CHUNK + (uint32_t)k * 64 + swz((uint32_t)(p & 31) * 2, (uint32_t)k);
        *reinterpret_cast<__nv_bfloat16*>(U_g + off) = __float2bfloat16(val);
        if (k == 0) tab_g[p] = (unsigned short)(d | (e << 8));
    }
    __syncthreads();

    if (t < 32) {
        float cAc = msh[t] * csh[t];
        #pragma unroll
        for (int o = 16; o > 0; o >>= 1) cAc += __shfl_xor_sync(0xffffffff, cAc, o);
        // warp Cholesky (SPD), lane = row
        float halflogdet = 0.f;
        for (int j = 0; j < 32; j++) {
            float ljj = sqrtf(Ash[j * 33 + j]);
            halflogdet += logf(ljj);
            float lij = (t > j) ? Ash[t * 33 + j] / ljj : 0.f;
            if (t > j) Ash[t * 33 + j] = lij;
            __syncwarp();
            if (t > j) {
                for (int c2 = j + 1; c2 <= t; c2++)
                    Ash[t * 33 + c2] -= lij * Ash[c2 * 33 + j];
            }
            __syncwarp();
        }
        if (t == 0)
            g_g[k] = logf(fabsf(w[k]) + 1e-37f) + halflogdet - 0.5f * cAc;
    }
}

// ---------------- main fused GEMM + logsumexp ----------------
constexpr int SMEM_U   = 0;               // 2 x 16384
constexpr int SMEM_F   = 32768;           // 2 x 8192
constexpr int SMEM_X   = 49152;           // 128 x 33 f32 = 16896
constexpr int SMEM_G   = 66048;           // 256 f32
constexpr int SMEM_P   = 67072;           // 128 x 4 f32
constexpr int SMEM_TAB = 69120;           // 608 u16 = 1216
constexpr int SMEM_RED = 70336;           // 8 max + 8 sum floats
constexpr int SMEM_DYN = 70400 + 1024;

DEV_INLINE uint32_t pack2(const float* xr, uint32_t t) {
    float v0 = xr[t & 255u]         * xr[(t >> 8)  & 255u];
    float v1 = xr[(t >> 16) & 255u] * xr[(t >> 24) & 255u];
    __nv_bfloat162 p2 = __floats2bfloat162_rn(v0, v1);
    return *(uint32_t*)&p2;
}

__global__ __launch_bounds__(512, 1)
void k_main(const float* __restrict__ points,
            const float* __restrict__ wts,
            const float* __restrict__ thr_p,
            float* __restrict__ out) {
    extern __shared__ char smem_raw[];
    char* smem = (char*)(((uintptr_t)smem_raw + 1023) & ~(uintptr_t)1023);
    uint32_t sb = smem_u32(smem);
    int tid = threadIdx.x;
    int wid = tid >> 5, lane = tid & 31;
    int g = lane >> 2, t4 = lane & 3;
    int warp_r = wid >> 2, warp_c = wid & 3;   // rows 32*warp_r, cols 64*warp_c (16 warps)
    int i0 = blockIdx.x * TILE_M;

    float* Xs = (float*)(smem + SMEM_X);
    float* gs = (float*)(smem + SMEM_G);
    float* redm = (float*)(smem + SMEM_RED);
    float* reds = (float*)(smem + SMEM_RED + 32);
    unsigned short* tab_s = (unsigned short*)(smem + SMEM_TAB);

    // loads: X tile (col 32 = 1.0), g', weights, tab
    #pragma unroll
    for (int q = 0; q < 8; q++) {
        int lin = tid + 512 * q;               // 0..4095
        Xs[(lin >> 5) * 33 + (lin & 31)] = points[(size_t)i0 * 32 + lin];
    }
    if (tid < 128) Xs[tid * 33 + 32] = 1.0f;
    if (tid < 256) {
        float gv = g_g[tid];
        gs[tid] = gv;
        float wv = fabsf(wts[tid]);
        #pragma unroll
        for (int o = 16; o > 0; o >>= 1) {
            gv = fmaxf(gv, __shfl_xor_sync(0xffffffff, gv, o));
            wv += __shfl_xor_sync(0xffffffff, wv, o);
        }
        if (lane == 0) { redm[wid] = gv; reds[wid] = wv; }
    }
    for (int p = tid; p < KTOT; p += 512) tab_s[p] = tab_g[p];
    float thrv = thr_p[0];
    __syncthreads();

    // F generation: thread -> row fr (0..127), quarter fq (8 cols = one sts_v4)
    int fr = tid >> 2, fq = tid & 3;
    const float* xr = Xs + fr * 33;
    uint32_t gen_base0 = (uint32_t)fr * 64 + (((uint32_t)fq * 16) ^ (((uint32_t)fr & 6u) << 3));

    // ldmatrix address precompute
    uint32_t offA[2][2], offB[2][4];
    {
        uint32_t lane15 = (uint32_t)(lane & 15);
        uint32_t colA = (uint32_t)(lane & 16);
        #pragma unroll
        for (int rt = 0; rt < 2; rt++) {
            uint32_t row = (uint32_t)(warp_r * 32 + rt * 16) + lane15;
            uint32_t m = (row & 6u) << 3;
            #pragma unroll
            for (int ks = 0; ks < 2; ks++)
                offA[ks][rt] = row * 64 + (((uint32_t)ks * 32 + colA) ^ m);
        }
        uint32_t colB = ((uint32_t)(lane & 8)) << 1;
        #pragma unroll
        for (int pr = 0; pr < 4; pr++) {
            uint32_t n = (uint32_t)(warp_c * 64 + pr * 16) + (((uint32_t)lane >> 1) & 8u) + (uint32_t)(lane & 7);
            uint32_t m = (n & 6u) << 3;
            #pragma unroll
            for (int ks = 0; ks < 2; ks++)
                offB[ks][pr] = n * 64 + (((uint32_t)ks * 32 + colB) ^ m);
        }
    }

    auto gen_F = [&](int c, int stage) {
        uint32_t base = sb + SMEM_F + (uint32_t)stage * F_CHUNK + gen_base0;
        uint4 q = *(const uint4*)(tab_s + c * 32 + fq * 8);
        uint32_t o0 = pack2(xr, q.x);
        uint32_t o1 = pack2(xr, q.y);
        uint32_t o2 = pack2(xr, q.z);
        uint32_t o3 = pack2(xr, q.w);
        sts_v4(base, o0, o1, o2, o3);
    };
    auto load_U = [&](int c, int stage) {
        const unsigned char* src = U_g + (size_t)c * U_CHUNK + (size_t)tid * 32;
        uint32_t dst = sb + SMEM_U + (uint32_t)stage * U_CHUNK + (uint32_t)tid * 32;
        cp_async16(dst, src);
        cp_async16(dst + 16, src + 16);
        CP_COMMIT();
    };

    float acc[2][8][4];
    #pragma unroll
    for (int a = 0; a < 2; a++)
        #pragma unroll
        for (int b = 0; b < 8; b++)
            #pragma unroll
            for (int j = 0; j < 4; j++) acc[a][b][j] = 0.f;

    // prologue
    gen_F(0, 0);
    load_U(0, 0);

    for (int c = 0; c < NCH; c++) {
        int s = c & 1;
        CP_WAIT0();
        __syncthreads();

        uint32_t fb = sb + SMEM_F + (uint32_t)s * F_CHUNK;
        uint32_t ub = sb + SMEM_U + (uint32_t)s * U_CHUNK;

        // A fragments for both k-steps
        uint32_t fA[2][2][4];
        #pragma unroll
        for (int ks = 0; ks < 2; ks++)
            #pragma unroll
            for (int rt = 0; rt < 2; rt++)
                ldsm4(fA[ks][rt], fb + offA[ks][rt]);

        // first B fragment
        uint32_t fBc[4], fBn[4];
        ldsm4(fBc, ub + offB[0][0]);

        if (c + 1 < NCH) { gen_F(c + 1, s ^ 1); load_U(c + 1, s ^ 1); }

        #pragma unroll
        for (int step = 0; step < 8; step++) {
            int ks = step >> 2, pr = step & 3;
            if (step < 7) {
                int ns = step + 1;
                ldsm4(fBn, ub + offB[ns >> 2][ns & 3]);
            }
            #pragma unroll
            for (int rt = 0; rt < 2; rt++) {
                mma16816(acc[rt][2 * pr],     fA[ks][rt], fBc[0], fBc[1]);
                mma16816(acc[rt][2 * pr + 1], fA[ks][rt], fBc[2], fBc[3]);
            }
            #pragma unroll
            for (int j = 0; j < 4; j++) fBc[j] = fBn[j];
        }
    }

    // -------- epilogue: exp-sum, reduce, log --------
    float Cv = fmaxf(fmaxf(fmaxf(redm[0], redm[1]), fmaxf(redm[2], redm[3])),
                     fmaxf(fmaxf(redm[4], redm[5]), fmaxf(redm[6], redm[7])));
    float LW = logf(reds[0] + reds[1] + reds[2] + reds[3] +
                    reds[4] + reds[5] + reds[6] + reds[7] + 1e-30f);

    float* part = (float*)(smem + SMEM_P);
    #pragma unroll
    for (int rt = 0; rt < 2; rt++) {
        float e_lo = 0.f, e_hi = 0.f;
        #pragma unroll
        for (int ct = 0; ct < 8; ct++) {
            int n0 = warp_c * 64 + ct * 8 + t4 * 2;
            float g0 = gs[n0] - Cv, g1 = gs[n0 + 1] - Cv;
            e_lo += __expf(acc[rt][ct][0] + g0) + __expf(acc[rt][ct][1] + g1);
            e_hi += __expf(acc[rt][ct][2] + g0) + __expf(acc[rt][ct][3] + g1);
        }
        e_lo += __shfl_xor_sync(0xffffffff, e_lo, 1);
        e_lo += __shfl_xor_sync(0xffffffff, e_lo, 2);
        e_hi += __shfl_xor_sync(0xffffffff, e_hi, 1);
        e_hi += __shfl_xor_sync(0xffffffff, e_hi, 2);
        if (t4 == 0) {
            int r = warp_r * 32 + rt * 16 + g;
            part[r * 4 + warp_c] = e_lo;
            part[(r + 8) * 4 + warp_c] = e_hi;
        }
    }
    __syncthreads();
    if (tid < 128) {
        float ssum = part[tid * 4] + part[tid * 4 + 1] + part[tid * 4 + 2] + part[tid * 4 + 3];
        out[i0 + tid] = logf(ssum) + Cv - LW - thrv;
    }
}

// ---------------- launch ----------------
extern "C" void kernel_launch(void* const* d_in, const int* in_sizes, int n_in,
                              void* d_out, int out_size) {
    const float* points  = (const float*)d_in[0];
    const float* centers = (const float*)d_in[1];
    const float* covs    = (const float*)d_in[2];
    const float* weights = (const float*)d_in[3];
    const float* thresh  = (const float*)d_in[4];
    float* out = (float*)d_out;

    int n = in_sizes[0] / D_DIM;     // 131072
    int grid = n / TILE_M;           // 1024

    k_prep<<<K_CL, 256>>>(centers, covs, weights);

    cudaFuncSetAttribute(k_main, cudaFuncAttributeMaxDynamicSharedMemorySize, SMEM_DYN);
    k_main<<<grid, 512, SMEM_DYN>>>(points, weights, thresh, out);
}

// round 6
// speedup vs baseline: 1.5466x; 1.2584x over previous
#include <cuda_runtime.h>
#include <cuda_bf16.h>
#include <cstdint>

#define DEV_INLINE __device__ __forceinline__

constexpr int N_PTS  = 131072;
constexpr int K_CL   = 256;
constexpr int D_DIM  = 32;

constexpr int TILE_M = 128;                 // points per CTA
constexpr int KTOT   = 576;                 // 528 pairs + 32 linear + 16 pad
constexpr int NCH    = KTOT / 32;           // 18 chunks of 32 k-columns
constexpr int U_CHUNK = K_CL * 64;          // 256 rows x 64B = 16384
constexpr int F_CHUNK = TILE_M * 64;        // 128 rows x 64B = 8192
constexpr int XD_STRIDE = 69;               // floats; 69%32=5 -> conflict-free rotated reads

// ---------------- device-global scratch ----------------
__device__ __align__(128) unsigned char U_g[NCH * U_CHUNK]; // pre-swizzled bf16 B operand
__device__ float g_g[K_CL];              // g'_k = log|w_k| + 0.5 logdet(A_k) - 0.5 c^T A c

// ---------------- helpers ----------------
DEV_INLINE uint32_t smem_u32(const void* p) {
    uint32_t a;
    asm("{ .reg .u64 t; cvta.to.shared.u64 t, %1; cvt.u32.u64 %0, t; }" : "=r"(a) : "l"(p));
    return a;
}
// row-dependent swizzle for 64B rows: rotate 16B chunks by (row>>1)&3
DEV_INLINE uint32_t swz(uint32_t c, uint32_t row) { return c ^ ((row & 6u) << 3); }

DEV_INLINE void sts_v4(uint32_t a, uint32_t v0, uint32_t v1, uint32_t v2, uint32_t v3) {
    asm volatile("st.shared.v4.b32 [%0], {%1,%2,%3,%4};"
                 :: "r"(a), "r"(v0), "r"(v1), "r"(v2), "r"(v3) : "memory");
}
DEV_INLINE void cp_async16(uint32_t dst, const void* src) {
    asm volatile("cp.async.cg.shared.global [%0], [%1], 16;"
                 :: "r"(dst), "l"(__cvta_generic_to_global(src)) : "memory");
}
#define CP_COMMIT() asm volatile("cp.async.commit_group;" ::: "memory")
#define CP_WAIT0()  asm volatile("cp.async.wait_group 0;" ::: "memory")

DEV_INLINE void ldsm4(uint32_t* r, uint32_t addr) {
    asm volatile("ldmatrix.sync.aligned.m8n8.x4.shared.b16 {%0,%1,%2,%3}, [%4];"
                 : "=r"(r[0]), "=r"(r[1]), "=r"(r[2]), "=r"(r[3]) : "r"(addr));
}

DEV_INLINE void mma16816(float* c, const uint32_t* a, uint32_t b0, uint32_t b1) {
    asm volatile(
        "mma.sync.aligned.m16n8k16.row.col.f32.bf16.bf16.f32 "
        "{%0,%1,%2,%3}, {%4,%5,%6,%7}, {%8,%9}, {%0,%1,%2,%3};"
        : "+f"(c[0]), "+f"(c[1]), "+f"(c[2]), "+f"(c[3])
        : "r"(a[0]), "r"(a[1]), "r"(a[2]), "r"(a[3]), "r"(b0), "r"(b1));
}

// ---------------- per-cluster prep ----------------
__global__ void k_prep(const float* __restrict__ centers,
                       const float* __restrict__ S,
                       const float* __restrict__ w) {
    __shared__ float Ssh[D_DIM * D_DIM];
    __shared__ float Ash[D_DIM * 33];
    __shared__ float csh[D_DIM];
    __shared__ float msh[D_DIM];
    int k = blockIdx.x, t = threadIdx.x;

    #pragma unroll
    for (int q = 0; q < 4; q++) Ssh[t + 256 * q] = S[k * 1024 + t + 256 * q];
    if (t < 32) csh[t] = centers[k * 32 + t];
    __syncthreads();

    #pragma unroll
    for (int q = 0; q < 4; q++) {
        int idx = t + 256 * q;
        int d = idx >> 5, f = idx & 31;
        float a = 0.f;
        #pragma unroll
        for (int e = 0; e < 32; e++) a += Ssh[d * 32 + e] * Ssh[f * 32 + e];
        Ash[d * 33 + f] = a;
    }
    __syncthreads();

    if (t < 32) {
        float m = 0.f;
        #pragma unroll
        for (int f = 0; f < 32; f++) m += Ash[t * 33 + f] * csh[f];
        msh[t] = m;
    }
    __syncthreads();

    // U entries (bf16, swizzled SMEM image), circular-offset pair layout:
    //  chunk c<16 , col j : coeff of x_j * x_{(j+c)&31} : c==0 ? -0.5 A_jj : -A_{j,(j+c)&31}
    //  chunk 16, col j<16 : -A_{j,j+16} ; col j>=16 : m_{j-16}
    //  chunk 17, col j<16 : m_{j+16}   ; col j>=16 : 0
    for (int p = t; p < KTOT; p += 256) {
        int c = p >> 5, j = p & 31;
        float val;
        if (c == 0)       val = -0.5f * Ash[j * 33 + j];
        else if (c < 16)  val = -Ash[j * 33 + ((j + c) & 31)];
        else if (c == 16) val = (j < 16) ? -Ash[j * 33 + j + 16] : msh[j - 16];
        else              val = (j < 16) ? msh[j + 16] : 0.f;
        uint32_t off = (uint32_t)c * U_CHUNK + (uint32_t)k * 64 + swz((uint32_t)j * 2, (uint32_t)k);
        *reinterpret_cast<__nv_bfloat16*>(U_g + off) = __float2bfloat16(val);
    }
    __syncthreads();

    if (t < 32) {
        float cAc = msh[t] * csh[t];
        #pragma unroll
        for (int o = 16; o > 0; o >>= 1) cAc += __shfl_xor_sync(0xffffffff, cAc, o);
        // warp Cholesky (SPD), lane = row
        float halflogdet = 0.f;
        for (int j = 0; j < 32; j++) {
            float ljj = sqrtf(Ash[j * 33 + j]);
            halflogdet += logf(ljj);
            float lij = (t > j) ? Ash[t * 33 + j] / ljj : 0.f;
            if (t > j) Ash[t * 33 + j] = lij;
            __syncwarp();
            if (t > j) {
                for (int c2 = j + 1; c2 <= t; c2++)
                    Ash[t * 33 + c2] -= lij * Ash[c2 * 33 + j];
            }
            __syncwarp();
        }
        if (t == 0)
            g_g[k] = logf(fabsf(w[t == 0 ? k : k]) + 1e-37f) + halflogdet - 0.5f * cAc;
    }
}

// ---------------- main fused GEMM + logsumexp ----------------
constexpr int SMEM_U   = 0;                          // 2 x 16384 = 32768
constexpr int SMEM_F   = 32768;                      // 2 x 8192 = 16384
constexpr int SMEM_X   = 49152;                      // 128 x 69 f32 = 35328
constexpr int SMEM_G   = 84480;                      // 256 f32
constexpr int SMEM_P   = 85504;                      // 128 x 4 f32
constexpr int SMEM_RED = 87552;                      // 8 max + 8 sum floats
constexpr int SMEM_DYN = 87616 + 1024;

__global__ __launch_bounds__(512, 1)
void k_main(const float* __restrict__ points,
            const float* __restrict__ wts,
            const float* __restrict__ thr_p,
            float* __restrict__ out) {
    extern __shared__ char smem_raw[];
    char* smem = (char*)(((uintptr_t)smem_raw + 1023) & ~(uintptr_t)1023);
    uint32_t sb = smem_u32(smem);
    int tid = threadIdx.x;
    int wid = tid >> 5, lane = tid & 31;
    int g = lane >> 2, t4 = lane & 3;
    int warp_r = wid >> 2, warp_c = wid & 3;   // rows 32*warp_r, cols 64*warp_c (16 warps)
    int i0 = blockIdx.x * TILE_M;

    float* Xd = (float*)(smem + SMEM_X);       // [128][69], cols 0..31 = x, 32..39 = x[0..7] dup
    float* gs = (float*)(smem + SMEM_G);
    float* redm = (float*)(smem + SMEM_RED);
    float* reds = (float*)(smem + SMEM_RED + 32);

    // loads: X tile (duplicated wrap cols), g', weights
    #pragma unroll
    for (int q = 0; q < 8; q++) {
        int lin = tid + 512 * q;               // 0..4095
        Xd[(lin >> 5) * XD_STRIDE + (lin & 31)] = points[(size_t)i0 * 32 + lin];
    }
    for (int lin = tid; lin < 1024; lin += 512) {
        int r = lin >> 3, cq = lin & 7;
        Xd[r * XD_STRIDE + 32 + cq] = points[(size_t)i0 * 32 + r * 32 + cq];
    }
    if (tid < 256) {
        float gv = g_g[tid];
        gs[tid] = gv;
        float wv = fabsf(wts[tid]);
        #pragma unroll
        for (int o = 16; o > 0; o >>= 1) {
            gv = fmaxf(gv, __shfl_xor_sync(0xffffffff, gv, o));
            wv += __shfl_xor_sync(0xffffffff, wv, o);
        }
        if (lane == 0) { redm[wid] = gv; reds[wid] = wv; }
    }
    float thrv = thr_p[0];
    __syncthreads();

    // F generation: thread -> row fr (0..127), quarter fq (8 cols)
    int fr = tid >> 2, fq = tid & 3;
    const float* srow = Xd + fr * XD_STRIDE;
    uint32_t gen_base0 = (uint32_t)fr * 64 + (((uint32_t)fq * 16) ^ (((uint32_t)fr & 6u) << 3));

    // own 8 x-values in registers
    float xself[8];
    #pragma unroll
    for (int jj = 0; jj < 8; jj++) xself[jj] = srow[fq * 8 + jj];

    // ldmatrix address precompute
    uint32_t offA[2][2], offB[2][4];
    {
        uint32_t lane15 = (uint32_t)(lane & 15);
        uint32_t colA = (uint32_t)(lane & 16);
        #pragma unroll
        for (int rt = 0; rt < 2; rt++) {
            uint32_t row = (uint32_t)(warp_r * 32 + rt * 16) + lane15;
            uint32_t m = (row & 6u) << 3;
            #pragma unroll
            for (int ks = 0; ks < 2; ks++)
                offA[ks][rt] = row * 64 + (((uint32_t)ks * 32 + colA) ^ m);
        }
        uint32_t colB = ((uint32_t)(lane & 8)) << 1;
        #pragma unroll
        for (int pr = 0; pr < 4; pr++) {
            uint32_t n = (uint32_t)(warp_c * 64 + pr * 16) + (((uint32_t)lane >> 1) & 8u) + (uint32_t)(lane & 7);
            uint32_t m = (n & 6u) << 3;
            #pragma unroll
            for (int ks = 0; ks < 2; ks++)
                offB[ks][pr] = n * 64 + (((uint32_t)ks * 32 + colB) ^ m);
        }
    }

    auto gen_F = [&](int c, int stage) {
        uint32_t base = sb + SMEM_F + (uint32_t)stage * F_CHUNK + gen_base0;
        int cc = (c >= 16) ? 16 : c;
        int b = (fq * 8 + cc) & 31;
        float xo[8];
        #pragma unroll
        for (int jj = 0; jj < 8; jj++) xo[jj] = srow[b + jj];   // conflict-free (stride 69)
        float v[8];
        if (c < 16) {
            #pragma unroll
            for (int jj = 0; jj < 8; jj++) v[jj] = xself[jj] * xo[jj];
        } else if (c == 16) {
            #pragma unroll
            for (int jj = 0; jj < 8; jj++) v[jj] = (fq < 2) ? xself[jj] * xo[jj] : xo[jj];
        } else {
            #pragma unroll
            for (int jj = 0; jj < 8; jj++) v[jj] = (fq < 2) ? xo[jj] : 0.f;
        }
        uint32_t o[4];
        #pragma unroll
        for (int q = 0; q < 4; q++) {
            __nv_bfloat162 p2 = __floats2bfloat162_rn(v[2 * q], v[2 * q + 1]);
            o[q] = *(uint32_t*)&p2;
        }
        sts_v4(base, o[0], o[1], o[2], o[3]);
    };
    auto load_U = [&](int c, int stage) {
        const unsigned char* src = U_g + (size_t)c * U_CHUNK + (size_t)tid * 32;
        uint32_t dst = sb + SMEM_U + (uint32_t)stage * U_CHUNK + (uint32_t)tid * 32;
        cp_async16(dst, src);
        cp_async16(dst + 16, src + 16);
        CP_COMMIT();
    };

    float acc[2][8][4];
    #pragma unroll
    for (int a = 0; a < 2; a++)
        #pragma unroll
        for (int b = 0; b < 8; b++)
            #pragma unroll
            for (int j = 0; j < 4; j++) acc[a][b][j] = 0.f;

    // prologue
    gen_F(0, 0);
    load_U(0, 0);

    for (int c = 0; c < NCH; c++) {
        int s = c & 1;
        CP_WAIT0();
        __syncthreads();

        uint32_t fb = sb + SMEM_F + (uint32_t)s * F_CHUNK;
        uint32_t ub = sb + SMEM_U + (uint32_t)s * U_CHUNK;

        // A fragments for both k-steps
        uint32_t fA[2][2][4];
        #pragma unroll
        for (int ks = 0; ks < 2; ks++)
            #pragma unroll
            for (int rt = 0; rt < 2; rt++)
                ldsm4(fA[ks][rt], fb + offA[ks][rt]);

        // first B fragment
        uint32_t fBc[4], fBn[4];
        ldsm4(fBc, ub + offB[0][0]);

        if (c + 1 < NCH) { gen_F(c + 1, s ^ 1); load_U(c + 1, s ^ 1); }

        #pragma unroll
        for (int step = 0; step < 8; step++) {
            int ks = step >> 2, pr = step & 3;
            if (step < 7) {
                int ns = step + 1;
                ldsm4(fBn, ub + offB[ns >> 2][ns & 3]);
            }
            #pragma unroll
            for (int rt = 0; rt < 2; rt++) {
                mma16816(acc[rt][2 * pr],     fA[ks][rt], fBc[0], fBc[1]);
                mma16816(acc[rt][2 * pr + 1], fA[ks][rt], fBc[2], fBc[3]);
            }
            #pragma unroll
            for (int j = 0; j < 4; j++) fBc[j] = fBn[j];
        }
    }

    // -------- epilogue: exp-sum, reduce, log --------
    float Cv = fmaxf(fmaxf(fmaxf(redm[0], redm[1]), fmaxf(redm[2], redm[3])),
                     fmaxf(fmaxf(redm[4], redm[5]), fmaxf(redm[6], redm[7])));
    float LW = logf(reds[0] + reds[1] + reds[2] + reds[3] +
                    reds[4] + reds[5] + reds[6] + reds[7] + 1e-30f);

    float* part = (float*)(smem + SMEM_P);
    #pragma unroll
    for (int rt = 0; rt < 2; rt++) {
        float e_lo = 0.f, e_hi = 0.f;
        #pragma unroll
        for (int ct = 0; ct < 8; ct++) {
            int n0 = warp_c * 64 + ct * 8 + t4 * 2;
            float g0 = gs[n0] - Cv, g1 = gs[n0 + 1] - Cv;
            e_lo += __expf(acc[rt][ct][0] + g0) + __expf(acc[rt][ct][1] + g1);
            e_hi += __expf(acc[rt][ct][2] + g0) + __expf(acc[rt][ct][3] + g1);
        }
        e_lo += __shfl_xor_sync(0xffffffff, e_lo, 1);
        e_lo += __shfl_xor_sync(0xffffffff, e_lo, 2);
        e_hi += __shfl_xor_sync(0xffffffff, e_hi, 1);
        e_hi += __shfl_xor_sync(0xffffffff, e_hi, 2);
        if (t4 == 0) {
            int r = warp_r * 32 + rt * 16 + g;
            part[r * 4 + warp_c] = e_lo;
            part[(r + 8) * 4 + warp_c] = e_hi;
        }
    }
    __syncthreads();
    if (tid < 128) {
        float ssum = part[tid * 4] + part[tid * 4 + 1] + part[tid * 4 + 2] + part[tid * 4 + 3];
        out[i0 + tid] = logf(ssum) + Cv - LW - thrv;
    }
}

// ---------------- launch ----------------
extern "C" void kernel_launch(void* const* d_in, const int* in_sizes, int n_in,
                              void* d_out, int out_size) {
    const float* points  = (const float*)d_in[0];
    const float* centers = (const float*)d_in[1];
    const float* covs    = (const float*)d_in[2];
    const float* weights = (const float*)d_in[3];
    const float* thresh  = (const float*)d_in[4];
    float* out = (float*)d_out;

    int n = in_sizes[0] / D_DIM;     // 131072
    int grid = n / TILE_M;           // 1024

    k_prep<<<K_CL, 256>>>(centers, covs, weights);

    cudaFuncSetAttribute(k_main, cudaFuncAttributeMaxDynamicSharedMemorySize, SMEM_DYN);
    k_main<<<grid, 512, SMEM_DYN>>>(points, weights, thresh, out);
}